// round 13
// baseline (speedup 1.0000x reference)
#include <cuda_runtime.h>
#include <cuda_bf16.h>
#include <math.h>
#include <stdint.h>

// Problem constants
#define NROWS 8192
#define DIM   256
#define BATCH 4096
#define INV_T      10.0f
#define INV_T_LN2  14.4269504088896340736f

#define NB        64                   // 8192 / 128 tiles per side
#define NTRI      (NB * (NB + 1) / 2)  // 2080 triangular CTAs

// Device-global scratch (no allocations allowed)
__device__ uint8_t        g_z8 [NROWS * DIM];   // normalized rows e4m3 (MMA operands)
__device__ float          g_rowsum[NROWS];      // sum_{j!=i} exp(sim_ij)
__device__ float          g_pos[BATCH];         // cos(z_i, z_{i+B})

// ---------------------------------------------------------------------------
__device__ __forceinline__ uint32_t smem_u32(const void* p) {
    uint32_t a;
    asm("{ .reg .u64 t; cvta.to.shared.u64 t, %1; cvt.u32.u64 %0, t; }" : "=r"(a) : "l"(p));
    return a;
}
__device__ __forceinline__ float ex2(float x) {
    asm("ex2.approx.f32 %0, %0;" : "+f"(x));
    return x;
}
// pack two floats -> e4m3x2 (lo -> low byte, hi -> high byte)
__device__ __forceinline__ uint16_t f2e4m3x2(float lo, float hi) {
    uint16_t r;
    asm("cvt.rn.satfinite.e4m3x2.f32 %0, %1, %2;" : "=h"(r) : "f"(hi), "f"(lo));
    return r;
}
#define CP_ASYNC16(s, g) \
    asm volatile("cp.async.cg.shared.global [%0], [%1], 16;" :: "r"(s), "l"(g) : "memory")
#define CP_COMMIT() asm volatile("cp.async.commit_group;" ::: "memory")
#define CP_WAIT(n)  asm volatile("cp.async.wait_group %0;" :: "n"(n) : "memory")

#define LDSM_X4(r0, r1, r2, r3, addr) \
    asm volatile("ldmatrix.sync.aligned.m8n8.x4.shared.b16 {%0,%1,%2,%3}, [%4];" \
                 : "=r"(r0), "=r"(r1), "=r"(r2), "=r"(r3) : "r"(addr))

// FP8 e4m3 MMA: m16n8k32, fp32 accumulate. Same reg shape as bf16 m16n8k16.
#define MMA16832(c0, c1, c2, c3, a0, a1, a2, a3, b0, b1) \
    asm volatile("mma.sync.aligned.m16n8k32.row.col.f32.e4m3.e4m3.f32 " \
                 "{%0,%1,%2,%3}, {%4,%5,%6,%7}, {%8,%9}, {%0,%1,%2,%3};" \
                 : "+f"(c0), "+f"(c1), "+f"(c2), "+f"(c3) \
                 : "r"(a0), "r"(a1), "r"(a2), "r"(a3), "r"(b0), "r"(b1))

// ---------------------------------------------------------------------------
// Kernel 1: one warp per pair (p, p+BATCH): normalize both rows -> g_z8 (e4m3),
// pos dot in registers (fp32 exact) -> g_pos, zero rowsums.
// ---------------------------------------------------------------------------
__global__ void k_prep(const float* __restrict__ z, float* __restrict__ out) {
    const int w    = threadIdx.x >> 5;
    const int lane = threadIdx.x & 31;
    const int p    = blockIdx.x * 8 + w;

    const float4* za4 = reinterpret_cast<const float4*>(z + (size_t)p * DIM);
    const float4* zb4 = reinterpret_cast<const float4*>(z + (size_t)(p + BATCH) * DIM);
    float4 a0 = za4[lane * 2], a1 = za4[lane * 2 + 1];
    float4 b0 = zb4[lane * 2], b1 = zb4[lane * 2 + 1];

    float ssa = a0.x*a0.x + a0.y*a0.y + a0.z*a0.z + a0.w*a0.w
              + a1.x*a1.x + a1.y*a1.y + a1.z*a1.z + a1.w*a1.w;
    float ssb = b0.x*b0.x + b0.y*b0.y + b0.z*b0.z + b0.w*b0.w
              + b1.x*b1.x + b1.y*b1.y + b1.z*b1.z + b1.w*b1.w;
    float dt  = a0.x*b0.x + a0.y*b0.y + a0.z*b0.z + a0.w*b0.w
              + a1.x*b1.x + a1.y*b1.y + a1.z*b1.z + a1.w*b1.w;
    #pragma unroll
    for (int o = 16; o; o >>= 1) {
        ssa += __shfl_xor_sync(0xffffffffu, ssa, o);
        ssb += __shfl_xor_sync(0xffffffffu, ssb, o);
        dt  += __shfl_xor_sync(0xffffffffu, dt,  o);
    }
    const float sca = rsqrtf(ssa);
    const float scb = rsqrtf(ssb);

    a0.x *= sca; a0.y *= sca; a0.z *= sca; a0.w *= sca;
    a1.x *= sca; a1.y *= sca; a1.z *= sca; a1.w *= sca;
    b0.x *= scb; b0.y *= scb; b0.z *= scb; b0.w *= scb;
    b1.x *= scb; b1.y *= scb; b1.z *= scb; b1.w *= scb;

    // Pack 8 normalized floats -> 8 e4m3 bytes per row per thread.
    uint16_t pa0 = f2e4m3x2(a0.x, a0.y), pa1 = f2e4m3x2(a0.z, a0.w);
    uint16_t pa2 = f2e4m3x2(a1.x, a1.y), pa3 = f2e4m3x2(a1.z, a1.w);
    uint2 pk;
    pk.x = (uint32_t)pa0 | ((uint32_t)pa1 << 16);
    pk.y = (uint32_t)pa2 | ((uint32_t)pa3 << 16);
    *reinterpret_cast<uint2*>(g_z8 + (size_t)p * DIM + lane * 8) = pk;

    pa0 = f2e4m3x2(b0.x, b0.y); pa1 = f2e4m3x2(b0.z, b0.w);
    pa2 = f2e4m3x2(b1.x, b1.y); pa3 = f2e4m3x2(b1.z, b1.w);
    pk.x = (uint32_t)pa0 | ((uint32_t)pa1 << 16);
    pk.y = (uint32_t)pa2 | ((uint32_t)pa3 << 16);
    *reinterpret_cast<uint2*>(g_z8 + (size_t)(p + BATCH) * DIM + lane * 8) = pk;

    if (lane == 0) {
        g_pos[p] = dt * sca * scb;
        g_rowsum[p] = 0.0f;
        g_rowsum[p + BATCH] = 0.0f;
        if (p == 0) out[0] = 0.0f;
    }
}

// ---------------------------------------------------------------------------
// Kernel 2: symmetric FP8 tensor-core sim GEMM + exp + rowsum.
// Triangular grid (bj >= bi). CTA: 128x128 tile, 8 warps (2x4), warp 64x32.
// FULL K=256 resident in SMEM (row = 256B), single load phase, 8 k32-steps
// of m16n8k32 e4m3 MMA with fragment double-buffering.
// ---------------------------------------------------------------------------
#define TILE_BYTES 32768            // 128 rows x 256B (256 e4m3)
#define DYN_SMEM   (2 * TILE_BYTES) // A + B = 64 KB

__global__ void __launch_bounds__(256, 2) k_sim() {
    extern __shared__ char dyn_smem[];
    const uint32_t smem = smem_u32(dyn_smem);

    // Triangular decode: blockIdx.x -> (bi, bj), bj >= bi.
    const int id = blockIdx.x;
    int bi = (int)(64.5f - sqrtf(64.5f * 64.5f - 2.0f * (float)id));
    while (bi * NB - bi * (bi - 1) / 2 > id) bi--;
    while ((bi + 1) * NB - (bi + 1) * bi / 2 <= id) bi++;
    const int bj = bi + (id - (bi * NB - bi * (bi - 1) / 2));
    const bool diag = (bi == bj);
    const int i0 = bi * 128, j0 = bj * 128;

    const int tid  = threadIdx.x;
    const int lane = tid & 31;
    const int wid  = tid >> 5;
    const int wm   = wid >> 2;       // 0..1 : warp row  (64 rows)
    const int wn   = wid & 3;        // 0..3 : warp col  (32 cols)

    const uint8_t* Ag = g_z8 + (size_t)i0 * DIM;
    const uint8_t* Bg = g_z8 + (size_t)j0 * DIM;

    const uint32_t abase = smem;
    const uint32_t bbase = smem + TILE_BYTES;

    // Load full tiles: 2048 16B chunks per operand; 8 per thread per operand.
    {
        #pragma unroll
        for (int it = 0; it < 8; it++) {
            const int idx = tid + it * 256;   // 0..2047
            const int r = idx >> 4, c = idx & 15;
            const uint32_t soff = (uint32_t)(r * 256 + ((c ^ (r & 7)) << 4));
            CP_ASYNC16(abase + soff, (const char*)(Ag + r * DIM + c * 16));
            CP_ASYNC16(bbase + soff, (const char*)(Bg + r * DIM + c * 16));
        }
        CP_COMMIT();
    }

    float acc[4][4][4];
    #pragma unroll
    for (int mt = 0; mt < 4; mt++)
        #pragma unroll
        for (int nt = 0; nt < 4; nt++)
            #pragma unroll
            for (int r = 0; r < 4; r++) acc[mt][nt][r] = 0.0f;

    // ldmatrix per-thread addressing (b16 view: 16B chunk = 16 fp8 along k).
    const int ar    = lane & 15;                           // A row within 16
    const int ahalf = lane >> 4;                           // A 16B-chunk half
    const int bn    = ((lane >> 4) & 1) * 8 + (lane & 7);  // B n-row within 16
    const int bhalf = (lane >> 3) & 1;                     // B 16B-chunk half

    uint32_t aoff[4], boff[2], amask[4], bmask[2];
    #pragma unroll
    for (int mt = 0; mt < 4; mt++) {
        const int row = wm * 64 + mt * 16 + ar;
        aoff[mt]  = (uint32_t)(row * 256);
        amask[mt] = (uint32_t)(row & 7);
    }
    #pragma unroll
    for (int p = 0; p < 2; p++) {
        const int row = wn * 32 + p * 16 + bn;
        boff[p]  = (uint32_t)(row * 256);
        bmask[p] = (uint32_t)(row & 7);
    }

    CP_WAIT(0);
    __syncthreads();

    uint32_t afr[2][4];       // A frags: double-buffered by m-tile
    uint32_t bfr[2][4][2];    // B frags: double-buffered by k-step

    // Preload k-step 0.
    {
        const uint32_t chb = (uint32_t)bhalf;
        LDSM_X4(bfr[0][0][0], bfr[0][0][1], bfr[0][1][0], bfr[0][1][1],
                bbase + boff[0] + ((chb ^ bmask[0]) << 4));
        LDSM_X4(bfr[0][2][0], bfr[0][2][1], bfr[0][3][0], bfr[0][3][1],
                bbase + boff[1] + ((chb ^ bmask[1]) << 4));
        const uint32_t cha = (uint32_t)ahalf;
        LDSM_X4(afr[0][0], afr[0][1], afr[0][2], afr[0][3],
                abase + aoff[0] + ((cha ^ amask[0]) << 4));
    }

    #pragma unroll
    for (int kk = 0; kk < 8; kk++) {        // 8 k-steps of 32
        const int bc = kk & 1;
        #pragma unroll
        for (int mt = 0; mt < 4; mt++) {
            const int ab = mt & 1;
            if (mt < 3) {
                const uint32_t cha = (uint32_t)(kk * 2) + (uint32_t)ahalf;
                LDSM_X4(afr[ab ^ 1][0], afr[ab ^ 1][1], afr[ab ^ 1][2], afr[ab ^ 1][3],
                        abase + aoff[mt + 1] + ((cha ^ amask[mt + 1]) << 4));
            } else if (kk < 7) {
                const uint32_t chb = (uint32_t)((kk + 1) * 2) + (uint32_t)bhalf;
                LDSM_X4(bfr[bc ^ 1][0][0], bfr[bc ^ 1][0][1], bfr[bc ^ 1][1][0], bfr[bc ^ 1][1][1],
                        bbase + boff[0] + ((chb ^ bmask[0]) << 4));
                LDSM_X4(bfr[bc ^ 1][2][0], bfr[bc ^ 1][2][1], bfr[bc ^ 1][3][0], bfr[bc ^ 1][3][1],
                        bbase + boff[1] + ((chb ^ bmask[1]) << 4));
                const uint32_t cha = (uint32_t)((kk + 1) * 2) + (uint32_t)ahalf;
                LDSM_X4(afr[ab ^ 1][0], afr[ab ^ 1][1], afr[ab ^ 1][2], afr[ab ^ 1][3],
                        abase + aoff[0] + ((cha ^ amask[0]) << 4));
            }
            #pragma unroll
            for (int nt = 0; nt < 4; nt++)
                MMA16832(acc[mt][nt][0], acc[mt][nt][1], acc[mt][nt][2], acc[mt][nt][3],
                         afr[ab][0], afr[ab][1], afr[ab][2], afr[ab][3],
                         bfr[bc][nt][0], bfr[bc][nt][1]);
        }
    }

    // ------------------------- epilogue -------------------------
    float rsum[8];   // [mt*2 + h] : rows wm*64 + mt*16 + h*8 + lane/4
    float csum[8];   // [nt*2 + e] : cols wn*32 + nt*8 + (lane%4)*2 + e
    #pragma unroll
    for (int i = 0; i < 8; i++) { rsum[i] = 0.0f; csum[i] = 0.0f; }

    const int q  = lane >> 2;
    const int e2 = (lane & 3) * 2;

    #pragma unroll
    for (int mt = 0; mt < 4; mt++) {
        #pragma unroll
        for (int nt = 0; nt < 4; nt++) {
            #pragma unroll
            for (int r = 0; r < 4; r++) {
                const int h = r >> 1;
                const int e = r & 1;
                float v = ex2(acc[mt][nt][r] * INV_T_LN2);
                if (diag) {
                    const int rl = wm * 64 + mt * 16 + h * 8 + q;
                    const int cl = wn * 32 + nt * 8 + e2 + e;
                    if (rl == cl) v = 0.0f;
                }
                rsum[mt * 2 + h] += v;
                csum[nt * 2 + e] += v;
            }
        }
    }

    #pragma unroll
    for (int i = 0; i < 8; i++) {
        rsum[i] += __shfl_xor_sync(0xffffffffu, rsum[i], 1);
        rsum[i] += __shfl_xor_sync(0xffffffffu, rsum[i], 2);
    }
    #pragma unroll
    for (int i = 0; i < 8; i++) {
        csum[i] += __shfl_xor_sync(0xffffffffu, csum[i], 4);
        csum[i] += __shfl_xor_sync(0xffffffffu, csum[i], 8);
        csum[i] += __shfl_xor_sync(0xffffffffu, csum[i], 16);
    }

    float* sred = reinterpret_cast<float*>(dyn_smem);            // [128][4]
    float* cred = sred + 128 * 4;                                // [128][2]
    __syncthreads();

    if ((lane & 3) == 0) {
        #pragma unroll
        for (int i = 0; i < 8; i++) {
            const int mt = i >> 1, h = i & 1;
            const int rl = wm * 64 + mt * 16 + h * 8 + q;
            sred[rl * 4 + wn] = rsum[i];
        }
    }
    if (!diag && (lane >> 2) == 0) {
        #pragma unroll
        for (int i = 0; i < 8; i++) {
            const int nt = i >> 1, e = i & 1;
            const int cl = wn * 32 + nt * 8 + (lane & 3) * 2 + e;
            cred[cl * 2 + wm] = csum[i];
        }
    }
    __syncthreads();

    if (tid < 128) {
        const float v = sred[tid * 4 + 0] + sred[tid * 4 + 1]
                      + sred[tid * 4 + 2] + sred[tid * 4 + 3];
        atomicAdd(&g_rowsum[i0 + tid], v);
        if (!diag) {
            const float w2 = cred[tid * 2 + 0] + cred[tid * 2 + 1];
            atomicAdd(&g_rowsum[j0 + tid], w2);
        }
    }
}

// ---------------------------------------------------------------------------
// Kernel 3: final reduction. loss = mean(log(rowsum) - pos/T).
// ---------------------------------------------------------------------------
__global__ void k_loss(float* __restrict__ out) {
    const int i    = blockIdx.x * 256 + threadIdx.x;
    const int lane = threadIdx.x & 31;
    float val = logf(g_rowsum[i]) - g_pos[i & (BATCH - 1)] * INV_T;
    #pragma unroll
    for (int o = 16; o; o >>= 1) val += __shfl_xor_sync(0xffffffffu, val, o);
    if (lane == 0) atomicAdd(out, val * (1.0f / (float)NROWS));
}

// ---------------------------------------------------------------------------
extern "C" void kernel_launch(void* const* d_in, const int* in_sizes, int n_in,
                              void* d_out, int out_size) {
    const float* z = (const float*)d_in[0];
    float* out = (float*)d_out;

    cudaFuncSetAttribute(k_sim, cudaFuncAttributeMaxDynamicSharedMemorySize, DYN_SMEM);

    k_prep<<<BATCH / 8, 256>>>(z, out);
    k_sim<<<NTRI, 256, DYN_SMEM>>>();
    k_loss<<<NROWS / 256, 256>>>(out);
}

// round 14
// speedup vs baseline: 1.0733x; 1.0733x over previous
#include <cuda_runtime.h>
#include <cuda_bf16.h>
#include <math.h>
#include <stdint.h>

// Problem constants
#define NROWS 8192
#define DIM   256
#define BATCH 4096
#define INV_T      10.0f
#define INV_T_LN2  14.4269504088896340736f

#define NB        64                   // 8192 / 128 tiles per side
#define NTRI      (NB * (NB + 1) / 2)  // 2080 triangular tiles
#define GRID_SIM  2072                 // 296 x 7 : blockIdx 0..7 take 2 tiles

// Device-global scratch (no allocations allowed)
__device__ __nv_bfloat16  g_znb[NROWS * DIM];   // normalized rows bf16 (MMA operands)
__device__ float          g_rowsum[NROWS];      // sum_{j!=i} exp(sim_ij)
__device__ float          g_pos[BATCH];         // cos(z_i, z_{i+B})

// ---------------------------------------------------------------------------
__device__ __forceinline__ uint32_t smem_u32(const void* p) {
    uint32_t a;
    asm("{ .reg .u64 t; cvta.to.shared.u64 t, %1; cvt.u32.u64 %0, t; }" : "=r"(a) : "l"(p));
    return a;
}
__device__ __forceinline__ float ex2(float x) {
    asm("ex2.approx.f32 %0, %0;" : "+f"(x));
    return x;
}
#define CP_ASYNC16(s, g) \
    asm volatile("cp.async.cg.shared.global [%0], [%1], 16;" :: "r"(s), "l"(g) : "memory")
#define CP_COMMIT() asm volatile("cp.async.commit_group;" ::: "memory")
#define CP_WAIT(n)  asm volatile("cp.async.wait_group %0;" :: "n"(n) : "memory")

#define LDSM_X4(r0, r1, r2, r3, addr) \
    asm volatile("ldmatrix.sync.aligned.m8n8.x4.shared.b16 {%0,%1,%2,%3}, [%4];" \
                 : "=r"(r0), "=r"(r1), "=r"(r2), "=r"(r3) : "r"(addr))

#define MMA16816(c0, c1, c2, c3, a0, a1, a2, a3, b0, b1) \
    asm volatile("mma.sync.aligned.m16n8k16.row.col.f32.bf16.bf16.f32 " \
                 "{%0,%1,%2,%3}, {%4,%5,%6,%7}, {%8,%9}, {%0,%1,%2,%3};" \
                 : "+f"(c0), "+f"(c1), "+f"(c2), "+f"(c3) \
                 : "r"(a0), "r"(a1), "r"(a2), "r"(a3), "r"(b0), "r"(b1))

// ---------------------------------------------------------------------------
// Kernel 1: one warp per TWO pairs (p, p+BATCH), (p+1, p+1+BATCH):
// normalize 4 rows -> g_znb, pos dots (fp32 exact) -> g_pos, zero rowsums.
// All 4 row loads issued up front for MLP; 6 shfl reductions interleaved.
// ---------------------------------------------------------------------------
__global__ void k_prep(const float* __restrict__ z, float* __restrict__ out) {
    const int w    = threadIdx.x >> 5;
    const int lane = threadIdx.x & 31;
    const int p    = blockIdx.x * 16 + w * 2;      // pairs p and p+1

    const float4* a4 = reinterpret_cast<const float4*>(z + (size_t)p * DIM);
    const float4* b4 = reinterpret_cast<const float4*>(z + (size_t)(p + BATCH) * DIM);
    const float4* c4 = reinterpret_cast<const float4*>(z + (size_t)(p + 1) * DIM);
    const float4* d4 = reinterpret_cast<const float4*>(z + (size_t)(p + 1 + BATCH) * DIM);
    float4 a0 = a4[lane * 2], a1 = a4[lane * 2 + 1];
    float4 b0 = b4[lane * 2], b1 = b4[lane * 2 + 1];
    float4 c0 = c4[lane * 2], c1 = c4[lane * 2 + 1];
    float4 d0 = d4[lane * 2], d1 = d4[lane * 2 + 1];

    float ssa = a0.x*a0.x + a0.y*a0.y + a0.z*a0.z + a0.w*a0.w
              + a1.x*a1.x + a1.y*a1.y + a1.z*a1.z + a1.w*a1.w;
    float ssb = b0.x*b0.x + b0.y*b0.y + b0.z*b0.z + b0.w*b0.w
              + b1.x*b1.x + b1.y*b1.y + b1.z*b1.z + b1.w*b1.w;
    float dt1 = a0.x*b0.x + a0.y*b0.y + a0.z*b0.z + a0.w*b0.w
              + a1.x*b1.x + a1.y*b1.y + a1.z*b1.z + a1.w*b1.w;
    float ssc = c0.x*c0.x + c0.y*c0.y + c0.z*c0.z + c0.w*c0.w
              + c1.x*c1.x + c1.y*c1.y + c1.z*c1.z + c1.w*c1.w;
    float ssd = d0.x*d0.x + d0.y*d0.y + d0.z*d0.z + d0.w*d0.w
              + d1.x*d1.x + d1.y*d1.y + d1.z*d1.z + d1.w*d1.w;
    float dt2 = c0.x*d0.x + c0.y*d0.y + c0.z*d0.z + c0.w*d0.w
              + c1.x*d1.x + c1.y*d1.y + c1.z*d1.z + c1.w*d1.w;
    #pragma unroll
    for (int o = 16; o; o >>= 1) {
        ssa += __shfl_xor_sync(0xffffffffu, ssa, o);
        ssb += __shfl_xor_sync(0xffffffffu, ssb, o);
        dt1 += __shfl_xor_sync(0xffffffffu, dt1, o);
        ssc += __shfl_xor_sync(0xffffffffu, ssc, o);
        ssd += __shfl_xor_sync(0xffffffffu, ssd, o);
        dt2 += __shfl_xor_sync(0xffffffffu, dt2, o);
    }
    const float sca = rsqrtf(ssa), scb = rsqrtf(ssb);
    const float scc = rsqrtf(ssc), scd = rsqrtf(ssd);

    __nv_bfloat162 q0, q1, q2, q3;
    uint4 pk;
    #define EMIT(v0, v1, sc, row) \
        q0 = __floats2bfloat162_rn(v0.x * sc, v0.y * sc); \
        q1 = __floats2bfloat162_rn(v0.z * sc, v0.w * sc); \
        q2 = __floats2bfloat162_rn(v1.x * sc, v1.y * sc); \
        q3 = __floats2bfloat162_rn(v1.z * sc, v1.w * sc); \
        pk.x = *reinterpret_cast<uint32_t*>(&q0); \
        pk.y = *reinterpret_cast<uint32_t*>(&q1); \
        pk.z = *reinterpret_cast<uint32_t*>(&q2); \
        pk.w = *reinterpret_cast<uint32_t*>(&q3); \
        *reinterpret_cast<uint4*>(g_znb + (size_t)(row) * DIM + lane * 8) = pk;

    EMIT(a0, a1, sca, p)
    EMIT(b0, b1, scb, p + BATCH)
    EMIT(c0, c1, scc, p + 1)
    EMIT(d0, d1, scd, p + 1 + BATCH)
    #undef EMIT

    if (lane == 0) {
        g_pos[p]     = dt1 * sca * scb;
        g_pos[p + 1] = dt2 * scc * scd;
        g_rowsum[p] = 0.0f;         g_rowsum[p + BATCH] = 0.0f;
        g_rowsum[p + 1] = 0.0f;     g_rowsum[p + 1 + BATCH] = 0.0f;
        if (p == 0) out[0] = 0.0f;
    }
}

// ---------------------------------------------------------------------------
// Kernel 2: symmetric bf16 tensor-core sim GEMM + exp + rowsum.
// Triangular tiles (bj >= bi), GRID_SIM=2072 CTAs; blockIdx 0..7 handle a
// second tile (id+2072) to kill the wave-quantization tail.
// CTA: 128x128 tile, 8 warps (2x4), warp 64x32. K=256 in 4 slabs of 64,
// triple-buffered cp.async; fragments software-pipelined. One sync per slab.
// ---------------------------------------------------------------------------
#define SLAB_BYTES 16384            // 128 rows x 128B (64 bf16)
#define BUF_BYTES  (2 * SLAB_BYTES) // A + B slab
#define DYN_SMEM   (3 * BUF_BYTES + 1024)

__global__ void __launch_bounds__(256, 2) k_sim() {
    extern __shared__ char dyn_smem[];
    const uint32_t smem = (smem_u32(dyn_smem) + 1023u) & ~1023u;

    const int tid  = threadIdx.x;
    const int lane = tid & 31;
    const int wid  = tid >> 5;
    const int wm   = wid >> 2;       // 0..1 : warp row  (64 rows)
    const int wn   = wid & 3;        // 0..3 : warp col  (32 cols)

    // ldmatrix per-thread addressing (tile-invariant)
    const int ar    = lane & 15;
    const int ahalf = lane >> 4;
    const int bn    = ((lane >> 4) & 1) * 8 + (lane & 7);
    const int bhalf = (lane >> 3) & 1;

    uint32_t aoff[4], boff[2], amask[4], bmask[2];
    #pragma unroll
    for (int mt = 0; mt < 4; mt++) {
        const int row = wm * 64 + mt * 16 + ar;
        aoff[mt]  = (uint32_t)(row * 128);
        amask[mt] = (uint32_t)(row & 7);
    }
    #pragma unroll
    for (int p = 0; p < 2; p++) {
        const int row = wn * 32 + p * 16 + bn;
        boff[p]  = (uint32_t)(row * 128);
        bmask[p] = (uint32_t)(row & 7);
    }
    const int lr = tid >> 3;
    const int lc = tid & 7;

    #pragma unroll 1
    for (int id = blockIdx.x; id < NTRI; id += GRID_SIM) {

        // Triangular decode: id -> (bi, bj), bj >= bi.
        int bi = (int)(64.5f - sqrtf(64.5f * 64.5f - 2.0f * (float)id));
        while (bi * NB - bi * (bi - 1) / 2 > id) bi--;
        while ((bi + 1) * NB - (bi + 1) * bi / 2 <= id) bi++;
        const int bj = bi + (id - (bi * NB - bi * (bi - 1) / 2));
        const bool diag = (bi == bj);
        const int i0 = bi * 128, j0 = bj * 128;

        const __nv_bfloat16* Ag = g_znb + (size_t)i0 * DIM;
        const __nv_bfloat16* Bg = g_znb + (size_t)j0 * DIM;

        auto issue_slab = [&](int s, int buf) {
            const uint32_t abase = smem + (uint32_t)buf * BUF_BYTES;
            const uint32_t bbase = abase + SLAB_BYTES;
            #pragma unroll
            for (int it = 0; it < 4; it++) {
                const int r = lr + it * 32;
                const uint32_t soff = (uint32_t)(r * 128 + ((lc ^ (r & 7)) << 4));
                CP_ASYNC16(abase + soff, (const char*)(Ag + r * DIM + s * 64 + lc * 8));
                CP_ASYNC16(bbase + soff, (const char*)(Bg + r * DIM + s * 64 + lc * 8));
            }
            CP_COMMIT();
        };

        float acc[4][4][4];
        #pragma unroll
        for (int mt = 0; mt < 4; mt++)
            #pragma unroll
            for (int nt = 0; nt < 4; nt++)
                #pragma unroll
                for (int r = 0; r < 4; r++) acc[mt][nt][r] = 0.0f;

        issue_slab(0, 0);
        issue_slab(1, 1);

        uint32_t afr[2][4];       // A frags: double-buffered by m-tile
        uint32_t bfr[2][4][2];    // B frags: double-buffered by k-step

        #pragma unroll 1
        for (int s = 0; s < 4; s++) {
            if (s < 3) { CP_WAIT(1); } else { CP_WAIT(0); }
            __syncthreads();              // slab s ready; buffer (s+2)%3 free
            if (s < 2) issue_slab(s + 2, (s + 2) % 3);

            const uint32_t abase = smem + (uint32_t)(s % 3) * BUF_BYTES;
            const uint32_t bbase = abase + SLAB_BYTES;

            // Preload k-step 0.
            {
                const uint32_t chb = (uint32_t)bhalf;
                LDSM_X4(bfr[0][0][0], bfr[0][0][1], bfr[0][1][0], bfr[0][1][1],
                        bbase + boff[0] + ((chb ^ bmask[0]) << 4));
                LDSM_X4(bfr[0][2][0], bfr[0][2][1], bfr[0][3][0], bfr[0][3][1],
                        bbase + boff[1] + ((chb ^ bmask[1]) << 4));
                const uint32_t cha = (uint32_t)ahalf;
                LDSM_X4(afr[0][0], afr[0][1], afr[0][2], afr[0][3],
                        abase + aoff[0] + ((cha ^ amask[0]) << 4));
            }

            #pragma unroll
            for (int kk = 0; kk < 4; kk++) {
                const int bc = kk & 1;
                #pragma unroll
                for (int mt = 0; mt < 4; mt++) {
                    const int ab = mt & 1;
                    if (mt < 3) {
                        const uint32_t cha = (uint32_t)(kk * 2) + (uint32_t)ahalf;
                        LDSM_X4(afr[ab ^ 1][0], afr[ab ^ 1][1], afr[ab ^ 1][2], afr[ab ^ 1][3],
                                abase + aoff[mt + 1] + ((cha ^ amask[mt + 1]) << 4));
                    } else if (kk < 3) {
                        const uint32_t chb = (uint32_t)((kk + 1) * 2) + (uint32_t)bhalf;
                        LDSM_X4(bfr[bc ^ 1][0][0], bfr[bc ^ 1][0][1], bfr[bc ^ 1][1][0], bfr[bc ^ 1][1][1],
                                bbase + boff[0] + ((chb ^ bmask[0]) << 4));
                        LDSM_X4(bfr[bc ^ 1][2][0], bfr[bc ^ 1][2][1], bfr[bc ^ 1][3][0], bfr[bc ^ 1][3][1],
                                bbase + boff[1] + ((chb ^ bmask[1]) << 4));
                        const uint32_t cha = (uint32_t)((kk + 1) * 2) + (uint32_t)ahalf;
                        LDSM_X4(afr[ab ^ 1][0], afr[ab ^ 1][1], afr[ab ^ 1][2], afr[ab ^ 1][3],
                                abase + aoff[0] + ((cha ^ amask[0]) << 4));
                    }
                    #pragma unroll
                    for (int nt = 0; nt < 4; nt++)
                        MMA16816(acc[mt][nt][0], acc[mt][nt][1], acc[mt][nt][2], acc[mt][nt][3],
                                 afr[ab][0], afr[ab][1], afr[ab][2], afr[ab][3],
                                 bfr[bc][nt][0], bfr[bc][nt][1]);
                }
            }
        }

        // ------------------------- epilogue -------------------------
        float rsum[8];   // [mt*2 + h] : rows wm*64 + mt*16 + h*8 + lane/4
        float csum[8];   // [nt*2 + e] : cols wn*32 + nt*8 + (lane%4)*2 + e
        #pragma unroll
        for (int i = 0; i < 8; i++) { rsum[i] = 0.0f; csum[i] = 0.0f; }

        const int q  = lane >> 2;
        const int e2 = (lane & 3) * 2;

        #pragma unroll
        for (int mt = 0; mt < 4; mt++) {
            #pragma unroll
            for (int nt = 0; nt < 4; nt++) {
                #pragma unroll
                for (int r = 0; r < 4; r++) {
                    const int h = r >> 1;
                    const int e = r & 1;
                    float v = ex2(acc[mt][nt][r] * INV_T_LN2);
                    if (diag) {
                        const int rl = wm * 64 + mt * 16 + h * 8 + q;
                        const int cl = wn * 32 + nt * 8 + e2 + e;
                        if (rl == cl) v = 0.0f;
                    }
                    rsum[mt * 2 + h] += v;
                    csum[nt * 2 + e] += v;
                }
            }
        }

        #pragma unroll
        for (int i = 0; i < 8; i++) {
            rsum[i] += __shfl_xor_sync(0xffffffffu, rsum[i], 1);
            rsum[i] += __shfl_xor_sync(0xffffffffu, rsum[i], 2);
        }
        #pragma unroll
        for (int i = 0; i < 8; i++) {
            csum[i] += __shfl_xor_sync(0xffffffffu, csum[i], 4);
            csum[i] += __shfl_xor_sync(0xffffffffu, csum[i], 8);
            csum[i] += __shfl_xor_sync(0xffffffffu, csum[i], 16);
        }

        float* sred = reinterpret_cast<float*>(dyn_smem);            // [128][4]
        float* cred = sred + 128 * 4;                                // [128][2]
        __syncthreads();   // all LDSM reads of operand smem done

        if ((lane & 3) == 0) {
            #pragma unroll
            for (int i = 0; i < 8; i++) {
                const int mt = i >> 1, h = i & 1;
                const int rl = wm * 64 + mt * 16 + h * 8 + q;
                sred[rl * 4 + wn] = rsum[i];
            }
        }
        if (!diag && (lane >> 2) == 0) {
            #pragma unroll
            for (int i = 0; i < 8; i++) {
                const int nt = i >> 1, e = i & 1;
                const int cl = wn * 32 + nt * 8 + (lane & 3) * 2 + e;
                cred[cl * 2 + wm] = csum[i];
            }
        }
        __syncthreads();

        if (tid < 128) {
            const float v = sred[tid * 4 + 0] + sred[tid * 4 + 1]
                          + sred[tid * 4 + 2] + sred[tid * 4 + 3];
            atomicAdd(&g_rowsum[i0 + tid], v);
            if (!diag) {
                const float w2 = cred[tid * 2 + 0] + cred[tid * 2 + 1];
                atomicAdd(&g_rowsum[j0 + tid], w2);
            }
        }
        __syncthreads();   // sred/cred reads done before next tile's loads
    }
}

// ---------------------------------------------------------------------------
// Kernel 3: final reduction. loss = mean(log(rowsum) - pos/T).
// ---------------------------------------------------------------------------
__global__ void k_loss(float* __restrict__ out) {
    const int i    = blockIdx.x * 256 + threadIdx.x;
    const int lane = threadIdx.x & 31;
    float val = logf(g_rowsum[i]) - g_pos[i & (BATCH - 1)] * INV_T;
    #pragma unroll
    for (int o = 16; o; o >>= 1) val += __shfl_xor_sync(0xffffffffu, val, o);
    if (lane == 0) atomicAdd(out, val * (1.0f / (float)NROWS));
}

// ---------------------------------------------------------------------------
extern "C" void kernel_launch(void* const* d_in, const int* in_sizes, int n_in,
                              void* d_out, int out_size) {
    const float* z = (const float*)d_in[0];
    float* out = (float*)d_out;

    cudaFuncSetAttribute(k_sim, cudaFuncAttributeMaxDynamicSharedMemorySize, DYN_SMEM);

    k_prep<<<BATCH / 16, 256>>>(z, out);
    k_sim<<<GRID_SIM, 256, DYN_SMEM>>>();
    k_loss<<<NROWS / 256, 256>>>(out);
}

// round 15
// speedup vs baseline: 1.1033x; 1.0280x over previous
#include <cuda_runtime.h>
#include <cuda_bf16.h>
#include <cuda_fp16.h>
#include <math.h>
#include <stdint.h>

// Problem constants
#define NROWS 8192
#define DIM   256
#define BATCH 4096
#define INV_T      10.0f
// sqrt(1/(T*ln2)) : pre-scale applied to both operands so acc = sim/(T*ln2)
#define SCL        3.7982825f

#define NB        64                   // 8192 / 128 tiles per side
#define NTRI      (NB * (NB + 1) / 2)  // 2080 triangular CTAs

// Device-global scratch (no allocations allowed)
__device__ __nv_bfloat16  g_znb[NROWS * DIM];   // normalized*SCL rows bf16
__device__ float          g_rowsum[NROWS];      // sum_{j!=i} exp(sim_ij)
__device__ float          g_pos[BATCH];         // cos(z_i, z_{i+B}) (exact fp32)

// ---------------------------------------------------------------------------
__device__ __forceinline__ uint32_t smem_u32(const void* p) {
    uint32_t a;
    asm("{ .reg .u64 t; cvta.to.shared.u64 t, %1; cvt.u32.u64 %0, t; }" : "=r"(a) : "l"(p));
    return a;
}
#define CP_ASYNC16(s, g) \
    asm volatile("cp.async.cg.shared.global [%0], [%1], 16;" :: "r"(s), "l"(g) : "memory")
#define CP_COMMIT() asm volatile("cp.async.commit_group;" ::: "memory")
#define CP_WAIT(n)  asm volatile("cp.async.wait_group %0;" :: "n"(n) : "memory")

#define LDSM_X4(r0, r1, r2, r3, addr) \
    asm volatile("ldmatrix.sync.aligned.m8n8.x4.shared.b16 {%0,%1,%2,%3}, [%4];" \
                 : "=r"(r0), "=r"(r1), "=r"(r2), "=r"(r3) : "r"(addr))

#define MMA16816(c0, c1, c2, c3, a0, a1, a2, a3, b0, b1) \
    asm volatile("mma.sync.aligned.m16n8k16.row.col.f32.bf16.bf16.f32 " \
                 "{%0,%1,%2,%3}, {%4,%5,%6,%7}, {%8,%9}, {%0,%1,%2,%3};" \
                 : "+f"(c0), "+f"(c1), "+f"(c2), "+f"(c3) \
                 : "r"(a0), "r"(a1), "r"(a2), "r"(a3), "r"(b0), "r"(b1))

// ---------------------------------------------------------------------------
// Kernel 1: one warp per pair (p, p+BATCH): normalize both rows, scale by SCL,
// emit bf16 -> g_znb; pos dot in fp32 -> g_pos; zero rowsums.
// ---------------------------------------------------------------------------
__global__ void k_prep(const float* __restrict__ z, float* __restrict__ out) {
    const int w    = threadIdx.x >> 5;
    const int lane = threadIdx.x & 31;
    const int p    = blockIdx.x * 8 + w;

    const float4* za4 = reinterpret_cast<const float4*>(z + (size_t)p * DIM);
    const float4* zb4 = reinterpret_cast<const float4*>(z + (size_t)(p + BATCH) * DIM);
    float4 a0 = za4[lane * 2], a1 = za4[lane * 2 + 1];
    float4 b0 = zb4[lane * 2], b1 = zb4[lane * 2 + 1];

    float ssa = a0.x*a0.x + a0.y*a0.y + a0.z*a0.z + a0.w*a0.w
              + a1.x*a1.x + a1.y*a1.y + a1.z*a1.z + a1.w*a1.w;
    float ssb = b0.x*b0.x + b0.y*b0.y + b0.z*b0.z + b0.w*b0.w
              + b1.x*b1.x + b1.y*b1.y + b1.z*b1.z + b1.w*b1.w;
    float dt  = a0.x*b0.x + a0.y*b0.y + a0.z*b0.z + a0.w*b0.w
              + a1.x*b1.x + a1.y*b1.y + a1.z*b1.z + a1.w*b1.w;
    #pragma unroll
    for (int o = 16; o; o >>= 1) {
        ssa += __shfl_xor_sync(0xffffffffu, ssa, o);
        ssb += __shfl_xor_sync(0xffffffffu, ssb, o);
        dt  += __shfl_xor_sync(0xffffffffu, dt,  o);
    }
    const float sca = rsqrtf(ssa);
    const float scb = rsqrtf(ssb);
    const float ka = sca * SCL;          // scaled for MMA operand
    const float kb = scb * SCL;

    __nv_bfloat162 q0 = __floats2bfloat162_rn(a0.x * ka, a0.y * ka);
    __nv_bfloat162 q1 = __floats2bfloat162_rn(a0.z * ka, a0.w * ka);
    __nv_bfloat162 q2 = __floats2bfloat162_rn(a1.x * ka, a1.y * ka);
    __nv_bfloat162 q3 = __floats2bfloat162_rn(a1.z * ka, a1.w * ka);
    uint4 pk;
    pk.x = *reinterpret_cast<uint32_t*>(&q0);
    pk.y = *reinterpret_cast<uint32_t*>(&q1);
    pk.z = *reinterpret_cast<uint32_t*>(&q2);
    pk.w = *reinterpret_cast<uint32_t*>(&q3);
    *reinterpret_cast<uint4*>(g_znb + (size_t)p * DIM + lane * 8) = pk;

    q0 = __floats2bfloat162_rn(b0.x * kb, b0.y * kb);
    q1 = __floats2bfloat162_rn(b0.z * kb, b0.w * kb);
    q2 = __floats2bfloat162_rn(b1.x * kb, b1.y * kb);
    q3 = __floats2bfloat162_rn(b1.z * kb, b1.w * kb);
    pk.x = *reinterpret_cast<uint32_t*>(&q0);
    pk.y = *reinterpret_cast<uint32_t*>(&q1);
    pk.z = *reinterpret_cast<uint32_t*>(&q2);
    pk.w = *reinterpret_cast<uint32_t*>(&q3);
    *reinterpret_cast<uint4*>(g_znb + (size_t)(p + BATCH) * DIM + lane * 8) = pk;

    if (lane == 0) {
        g_pos[p] = dt * sca * scb;
        g_rowsum[p] = 0.0f;
        g_rowsum[p + BATCH] = 0.0f;
        if (p == 0) out[0] = 0.0f;
    }
}

// ---------------------------------------------------------------------------
// Kernel 2: symmetric bf16 tensor-core sim GEMM + fp16x2 exp2 + rowsum.
// Triangular grid (bj >= bi). CTA: 128x128 tile, 8 warps (2x4), warp 64x32.
// K=256 in 4 slabs of 64, triple-buffered cp.async; fragments software-
// pipelined. acc is already the exp2 argument (operands pre-scaled by SCL).
// ---------------------------------------------------------------------------
#define SLAB_BYTES 16384            // 128 rows x 128B (64 bf16)
#define BUF_BYTES  (2 * SLAB_BYTES) // A + B slab
#define DYN_SMEM   (3 * BUF_BYTES + 1024)

__global__ void __launch_bounds__(256, 2) k_sim() {
    extern __shared__ char dyn_smem[];
    const uint32_t smem = (smem_u32(dyn_smem) + 1023u) & ~1023u;

    // Triangular decode: blockIdx.x -> (bi, bj), bj >= bi.
    const int id = blockIdx.x;
    int bi = (int)(64.5f - sqrtf(64.5f * 64.5f - 2.0f * (float)id));
    while (bi * NB - bi * (bi - 1) / 2 > id) bi--;
    while ((bi + 1) * NB - (bi + 1) * bi / 2 <= id) bi++;
    const int bj = bi + (id - (bi * NB - bi * (bi - 1) / 2));
    const bool diag = (bi == bj);
    const int i0 = bi * 128, j0 = bj * 128;

    const int tid  = threadIdx.x;
    const int lane = tid & 31;
    const int wid  = tid >> 5;
    const int wm   = wid >> 2;       // 0..1 : warp row  (64 rows)
    const int wn   = wid & 3;        // 0..3 : warp col  (32 cols)

    const __nv_bfloat16* Ag = g_znb + (size_t)i0 * DIM;
    const __nv_bfloat16* Bg = g_znb + (size_t)j0 * DIM;

    const int lr = tid >> 3;
    const int lc = tid & 7;
    auto issue_slab = [&](int s, int buf) {
        const uint32_t abase = smem + (uint32_t)buf * BUF_BYTES;
        const uint32_t bbase = abase + SLAB_BYTES;
        #pragma unroll
        for (int it = 0; it < 4; it++) {
            const int r = lr + it * 32;
            const uint32_t soff = (uint32_t)(r * 128 + ((lc ^ (r & 7)) << 4));
            CP_ASYNC16(abase + soff, (const char*)(Ag + r * DIM + s * 64 + lc * 8));
            CP_ASYNC16(bbase + soff, (const char*)(Bg + r * DIM + s * 64 + lc * 8));
        }
        CP_COMMIT();
    };

    float acc[4][4][4];
    #pragma unroll
    for (int mt = 0; mt < 4; mt++)
        #pragma unroll
        for (int nt = 0; nt < 4; nt++)
            #pragma unroll
            for (int r = 0; r < 4; r++) acc[mt][nt][r] = 0.0f;

    // ldmatrix per-thread addressing
    const int ar    = lane & 15;
    const int ahalf = lane >> 4;
    const int bn    = ((lane >> 4) & 1) * 8 + (lane & 7);
    const int bhalf = (lane >> 3) & 1;

    uint32_t aoff[4], boff[2], amask[4], bmask[2];
    #pragma unroll
    for (int mt = 0; mt < 4; mt++) {
        const int row = wm * 64 + mt * 16 + ar;
        aoff[mt]  = (uint32_t)(row * 128);
        amask[mt] = (uint32_t)(row & 7);
    }
    #pragma unroll
    for (int p = 0; p < 2; p++) {
        const int row = wn * 32 + p * 16 + bn;
        boff[p]  = (uint32_t)(row * 128);
        bmask[p] = (uint32_t)(row & 7);
    }

    issue_slab(0, 0);
    issue_slab(1, 1);

    uint32_t afr[2][4];       // A frags: double-buffered by m-tile
    uint32_t bfr[2][4][2];    // B frags: double-buffered by k-step

    #pragma unroll 1
    for (int s = 0; s < 4; s++) {
        if (s < 3) { CP_WAIT(1); } else { CP_WAIT(0); }
        __syncthreads();                  // slab s ready; buffer (s+2)%3 free
        if (s < 2) issue_slab(s + 2, (s + 2) % 3);

        const uint32_t abase = smem + (uint32_t)(s % 3) * BUF_BYTES;
        const uint32_t bbase = abase + SLAB_BYTES;

        // Preload k-step 0.
        {
            const uint32_t chb = (uint32_t)bhalf;
            LDSM_X4(bfr[0][0][0], bfr[0][0][1], bfr[0][1][0], bfr[0][1][1],
                    bbase + boff[0] + ((chb ^ bmask[0]) << 4));
            LDSM_X4(bfr[0][2][0], bfr[0][2][1], bfr[0][3][0], bfr[0][3][1],
                    bbase + boff[1] + ((chb ^ bmask[1]) << 4));
            const uint32_t cha = (uint32_t)ahalf;
            LDSM_X4(afr[0][0], afr[0][1], afr[0][2], afr[0][3],
                    abase + aoff[0] + ((cha ^ amask[0]) << 4));
        }

        #pragma unroll
        for (int kk = 0; kk < 4; kk++) {
            const int bc = kk & 1;
            #pragma unroll
            for (int mt = 0; mt < 4; mt++) {
                const int ab = mt & 1;
                if (mt < 3) {
                    const uint32_t cha = (uint32_t)(kk * 2) + (uint32_t)ahalf;
                    LDSM_X4(afr[ab ^ 1][0], afr[ab ^ 1][1], afr[ab ^ 1][2], afr[ab ^ 1][3],
                            abase + aoff[mt + 1] + ((cha ^ amask[mt + 1]) << 4));
                } else if (kk < 3) {
                    const uint32_t chb = (uint32_t)((kk + 1) * 2) + (uint32_t)bhalf;
                    LDSM_X4(bfr[bc ^ 1][0][0], bfr[bc ^ 1][0][1], bfr[bc ^ 1][1][0], bfr[bc ^ 1][1][1],
                            bbase + boff[0] + ((chb ^ bmask[0]) << 4));
                    LDSM_X4(bfr[bc ^ 1][2][0], bfr[bc ^ 1][2][1], bfr[bc ^ 1][3][0], bfr[bc ^ 1][3][1],
                            bbase + boff[1] + ((chb ^ bmask[1]) << 4));
                    const uint32_t cha = (uint32_t)((kk + 1) * 2) + (uint32_t)ahalf;
                    LDSM_X4(afr[ab ^ 1][0], afr[ab ^ 1][1], afr[ab ^ 1][2], afr[ab ^ 1][3],
                            abase + aoff[0] + ((cha ^ amask[0]) << 4));
                }
                #pragma unroll
                for (int nt = 0; nt < 4; nt++)
                    MMA16816(acc[mt][nt][0], acc[mt][nt][1], acc[mt][nt][2], acc[mt][nt][3],
                             afr[ab][0], afr[ab][1], afr[ab][2], afr[ab][3],
                             bfr[bc][nt][0], bfr[bc][nt][1]);
            }
        }
    }

    // ------------------- epilogue (fp16x2 exp2) -------------------
    // acc pair (r=2h, r=2h+1) = adjacent cols (e0, e1) of row q(+8h).
    __half2 rsum2[8];   // [mt*2+h] : lo+hi both belong to the row
    __half2 csum2[4];   // [nt]     : lo -> col e0, hi -> col e1
    #pragma unroll
    for (int i = 0; i < 8; i++) rsum2[i] = __floats2half2_rn(0.0f, 0.0f);
    #pragma unroll
    for (int i = 0; i < 4; i++) csum2[i] = __floats2half2_rn(0.0f, 0.0f);

    const int q  = lane >> 2;
    const int e2 = (lane & 3) * 2;

    #pragma unroll
    for (int mt = 0; mt < 4; mt++) {
        #pragma unroll
        for (int nt = 0; nt < 4; nt++) {
            #pragma unroll
            for (int h = 0; h < 2; h++) {
                float v0 = acc[mt][nt][h * 2 + 0];
                float v1 = acc[mt][nt][h * 2 + 1];
                if (diag) {
                    const int rl = wm * 64 + mt * 16 + h * 8 + q;
                    const int c0 = wn * 32 + nt * 8 + e2;
                    if (rl == c0)     v0 = -100.0f;
                    if (rl == c0 + 1) v1 = -100.0f;
                }
                __half2 e = h2exp2(__floats2half2_rn(v0, v1));
                rsum2[mt * 2 + h] = __hadd2(rsum2[mt * 2 + h], e);
                csum2[nt]         = __hadd2(csum2[nt], e);
            }
        }
    }

    float rsum[8], csum[8];
    #pragma unroll
    for (int i = 0; i < 8; i++)
        rsum[i] = __low2float(rsum2[i]) + __high2float(rsum2[i]);
    #pragma unroll
    for (int nt = 0; nt < 4; nt++) {
        csum[nt * 2 + 0] = __low2float(csum2[nt]);
        csum[nt * 2 + 1] = __high2float(csum2[nt]);
    }

    #pragma unroll
    for (int i = 0; i < 8; i++) {
        rsum[i] += __shfl_xor_sync(0xffffffffu, rsum[i], 1);
        rsum[i] += __shfl_xor_sync(0xffffffffu, rsum[i], 2);
    }
    #pragma unroll
    for (int i = 0; i < 8; i++) {
        csum[i] += __shfl_xor_sync(0xffffffffu, csum[i], 4);
        csum[i] += __shfl_xor_sync(0xffffffffu, csum[i], 8);
        csum[i] += __shfl_xor_sync(0xffffffffu, csum[i], 16);
    }

    float* sred = reinterpret_cast<float*>(dyn_smem);            // [128][4]
    float* cred = sred + 128 * 4;                                // [128][2]
    __syncthreads();

    if ((lane & 3) == 0) {
        #pragma unroll
        for (int i = 0; i < 8; i++) {
            const int mt = i >> 1, h = i & 1;
            const int rl = wm * 64 + mt * 16 + h * 8 + q;
            sred[rl * 4 + wn] = rsum[i];
        }
    }
    if (!diag && (lane >> 2) == 0) {
        #pragma unroll
        for (int i = 0; i < 8; i++) {
            const int nt = i >> 1, e = i & 1;
            const int cl = wn * 32 + nt * 8 + (lane & 3) * 2 + e;
            cred[cl * 2 + wm] = csum[i];
        }
    }
    __syncthreads();

    if (tid < 128) {
        const float v = sred[tid * 4 + 0] + sred[tid * 4 + 1]
                      + sred[tid * 4 + 2] + sred[tid * 4 + 3];
        atomicAdd(&g_rowsum[i0 + tid], v);
        if (!diag) {
            const float w2 = cred[tid * 2 + 0] + cred[tid * 2 + 1];
            atomicAdd(&g_rowsum[j0 + tid], w2);
        }
    }
}

// ---------------------------------------------------------------------------
// Kernel 3: final reduction. loss = mean(log(rowsum) - pos/T).
// ---------------------------------------------------------------------------
__global__ void k_loss(float* __restrict__ out) {
    const int i    = blockIdx.x * 256 + threadIdx.x;
    const int lane = threadIdx.x & 31;
    float val = logf(g_rowsum[i]) - g_pos[i & (BATCH - 1)] * INV_T;
    #pragma unroll
    for (int o = 16; o; o >>= 1) val += __shfl_xor_sync(0xffffffffu, val, o);
    if (lane == 0) atomicAdd(out, val * (1.0f / (float)NROWS));
}

// ---------------------------------------------------------------------------
extern "C" void kernel_launch(void* const* d_in, const int* in_sizes, int n_in,
                              void* d_out, int out_size) {
    const float* z = (const float*)d_in[0];
    float* out = (float*)d_out;

    cudaFuncSetAttribute(k_sim, cudaFuncAttributeMaxDynamicSharedMemorySize, DYN_SMEM);

    k_prep<<<BATCH / 8, 256>>>(z, out);
    k_sim<<<NTRI, 256, DYN_SMEM>>>();
    k_loss<<<NROWS / 256, 256>>>(out);
}

// round 17
// speedup vs baseline: 1.1039x; 1.0006x over previous
#include <cuda_runtime.h>
#include <cuda_bf16.h>
#include <cuda_fp16.h>
#include <math.h>
#include <stdint.h>

// Problem constants
#define NROWS 8192
#define DIM   256
#define BATCH 4096
#define INV_T      10.0f
// sqrt(1/(T*ln2)) : pre-scale applied to both operands so acc = sim/(T*ln2)
#define SCL        3.7982825f

#define NB        64                   // 8192 / 128 tiles per side
#define NTRI      (NB * (NB + 1) / 2)  // 2080 triangular CTAs

// Device-global scratch (no allocations allowed)
__device__ __nv_bfloat16  g_znb[NROWS * DIM];   // normalized*SCL rows bf16
__device__ float          g_rowsum[NROWS];      // sum_{j!=i} exp(sim_ij)
__device__ float          g_pos[BATCH];         // cos(z_i, z_{i+B}) (exact fp32)

// ---------------------------------------------------------------------------
__device__ __forceinline__ uint32_t smem_u32(const void* p) {
    uint32_t a;
    asm("{ .reg .u64 t; cvta.to.shared.u64 t, %1; cvt.u32.u64 %0, t; }" : "=r"(a) : "l"(p));
    return a;
}
#define CP_ASYNC16(s, g) \
    asm volatile("cp.async.cg.shared.global [%0], [%1], 16;" :: "r"(s), "l"(g) : "memory")
#define CP_COMMIT() asm volatile("cp.async.commit_group;" ::: "memory")
#define CP_WAIT(n)  asm volatile("cp.async.wait_group %0;" :: "n"(n) : "memory")

#define LDSM_X4(r0, r1, r2, r3, addr) \
    asm volatile("ldmatrix.sync.aligned.m8n8.x4.shared.b16 {%0,%1,%2,%3}, [%4];" \
                 : "=r"(r0), "=r"(r1), "=r"(r2), "=r"(r3) : "r"(addr))

#define MMA16816(c0, c1, c2, c3, a0, a1, a2, a3, b0, b1) \
    asm volatile("mma.sync.aligned.m16n8k16.row.col.f32.bf16.bf16.f32 " \
                 "{%0,%1,%2,%3}, {%4,%5,%6,%7}, {%8,%9}, {%0,%1,%2,%3};" \
                 : "+f"(c0), "+f"(c1), "+f"(c2), "+f"(c3) \
                 : "r"(a0), "r"(a1), "r"(a2), "r"(a3), "r"(b0), "r"(b1))

// ---------------------------------------------------------------------------
// Kernel 1: one warp per pair (p, p+BATCH): normalize both rows, scale by SCL,
// emit bf16 -> g_znb; pos dot in fp32 -> g_pos; zero rowsums.
// ---------------------------------------------------------------------------
__global__ void k_prep(const float* __restrict__ z, float* __restrict__ out) {
    const int w    = threadIdx.x >> 5;
    const int lane = threadIdx.x & 31;
    const int p    = blockIdx.x * 8 + w;

    const float4* za4 = reinterpret_cast<const float4*>(z + (size_t)p * DIM);
    const float4* zb4 = reinterpret_cast<const float4*>(z + (size_t)(p + BATCH) * DIM);
    float4 a0 = za4[lane * 2], a1 = za4[lane * 2 + 1];
    float4 b0 = zb4[lane * 2], b1 = zb4[lane * 2 + 1];

    float ssa = a0.x*a0.x + a0.y*a0.y + a0.z*a0.z + a0.w*a0.w
              + a1.x*a1.x + a1.y*a1.y + a1.z*a1.z + a1.w*a1.w;
    float ssb = b0.x*b0.x + b0.y*b0.y + b0.z*b0.z + b0.w*b0.w
              + b1.x*b1.x + b1.y*b1.y + b1.z*b1.z + b1.w*b1.w;
    float dt  = a0.x*b0.x + a0.y*b0.y + a0.z*b0.z + a0.w*b0.w
              + a1.x*b1.x + a1.y*b1.y + a1.z*b1.z + a1.w*b1.w;
    #pragma unroll
    for (int o = 16; o; o >>= 1) {
        ssa += __shfl_xor_sync(0xffffffffu, ssa, o);
        ssb += __shfl_xor_sync(0xffffffffu, ssb, o);
        dt  += __shfl_xor_sync(0xffffffffu, dt,  o);
    }
    const float sca = rsqrtf(ssa);
    const float scb = rsqrtf(ssb);
    const float ka = sca * SCL;
    const float kb = scb * SCL;

    __nv_bfloat162 q0 = __floats2bfloat162_rn(a0.x * ka, a0.y * ka);
    __nv_bfloat162 q1 = __floats2bfloat162_rn(a0.z * ka, a0.w * ka);
    __nv_bfloat162 q2 = __floats2bfloat162_rn(a1.x * ka, a1.y * ka);
    __nv_bfloat162 q3 = __floats2bfloat162_rn(a1.z * ka, a1.w * ka);
    uint4 pk;
    pk.x = *reinterpret_cast<uint32_t*>(&q0);
    pk.y = *reinterpret_cast<uint32_t*>(&q1);
    pk.z = *reinterpret_cast<uint32_t*>(&q2);
    pk.w = *reinterpret_cast<uint32_t*>(&q3);
    *reinterpret_cast<uint4*>(g_znb + (size_t)p * DIM + lane * 8) = pk;

    q0 = __floats2bfloat162_rn(b0.x * kb, b0.y * kb);
    q1 = __floats2bfloat162_rn(b0.z * kb, b0.w * kb);
    q2 = __floats2bfloat162_rn(b1.x * kb, b1.y * kb);
    q3 = __floats2bfloat162_rn(b1.z * kb, b1.w * kb);
    pk.x = *reinterpret_cast<uint32_t*>(&q0);
    pk.y = *reinterpret_cast<uint32_t*>(&q1);
    pk.z = *reinterpret_cast<uint32_t*>(&q2);
    pk.w = *reinterpret_cast<uint32_t*>(&q3);
    *reinterpret_cast<uint4*>(g_znb + (size_t)(p + BATCH) * DIM + lane * 8) = pk;

    if (lane == 0) {
        g_pos[p] = dt * sca * scb;
        g_rowsum[p] = 0.0f;
        g_rowsum[p + BATCH] = 0.0f;
        if (p == 0) out[0] = 0.0f;
    }
}

// ---------------------------------------------------------------------------
// Kernel 2: symmetric bf16 tensor-core sim GEMM + fp16x2 exp2 + rowsum.
// Triangular grid (bj >= bi). CTA: 128x128 tile, FOUR warps (2x2 grid),
// warp tile 64x64 -> 33% less LDSM traffic (crossbar was co-binding with
// tensor pipe). K=256 in 4 slabs of 64, triple-buffered cp.async; fragment
// sets double-buffered by k-step. 2 CTA/SM via __launch_bounds__(128, 2).
// ---------------------------------------------------------------------------
#define SLAB_BYTES 16384            // 128 rows x 128B (64 bf16)
#define BUF_BYTES  (2 * SLAB_BYTES) // A + B slab
#define DYN_SMEM   (3 * BUF_BYTES + 1024)

__global__ void __launch_bounds__(128, 2) k_sim() {
    extern __shared__ char dyn_smem[];
    const uint32_t smem = (smem_u32(dyn_smem) + 1023u) & ~1023u;

    // Triangular decode: blockIdx.x -> (bi, bj), bj >= bi.
    const int id = blockIdx.x;
    int bi = (int)(64.5f - sqrtf(64.5f * 64.5f - 2.0f * (float)id));
    while (bi * NB - bi * (bi - 1) / 2 > id) bi--;
    while ((bi + 1) * NB - (bi + 1) * bi / 2 <= id) bi++;
    const int bj = bi + (id - (bi * NB - bi * (bi - 1) / 2));
    const bool diag = (bi == bj);
    const int i0 = bi * 128, j0 = bj * 128;

    const int tid  = threadIdx.x;
    const int lane = tid & 31;
    const int wid  = tid >> 5;       // 0..3
    const int wm   = wid >> 1;       // 0..1 : warp row (64 rows)
    const int wn   = wid & 1;        // 0..1 : warp col (64 cols)

    const __nv_bfloat16* Ag = g_znb + (size_t)i0 * DIM;
    const __nv_bfloat16* Bg = g_znb + (size_t)j0 * DIM;

    // gmem->smem: slab = 1024 chunks of 16B per operand; 8 per thread each.
    const int lr = tid >> 3;               // 0..15
    const int lc = tid & 7;
    auto issue_slab = [&](int s, int buf) {
        const uint32_t abase = smem + (uint32_t)buf * BUF_BYTES;
        const uint32_t bbase = abase + SLAB_BYTES;
        #pragma unroll
        for (int it = 0; it < 8; it++) {
            const int r = lr + it * 16;
            const uint32_t soff = (uint32_t)(r * 128 + ((lc ^ (r & 7)) << 4));
            CP_ASYNC16(abase + soff, (const char*)(Ag + r * DIM + s * 64 + lc * 8));
            CP_ASYNC16(bbase + soff, (const char*)(Bg + r * DIM + s * 64 + lc * 8));
        }
        CP_COMMIT();
    };

    float acc[4][8][4];   // [mt][nt][r] : warp tile 64x64
    #pragma unroll
    for (int mt = 0; mt < 4; mt++)
        #pragma unroll
        for (int nt = 0; nt < 8; nt++)
            #pragma unroll
            for (int r = 0; r < 4; r++) acc[mt][nt][r] = 0.0f;

    // ldmatrix per-thread addressing
    const int ar    = lane & 15;
    const int ahalf = lane >> 4;
    const int bn    = ((lane >> 4) & 1) * 8 + (lane & 7);
    const int bhalf = (lane >> 3) & 1;

    uint32_t aoff[4], amask[4], boff[4], bmask[4];
    #pragma unroll
    for (int mt = 0; mt < 4; mt++) {
        const int row = wm * 64 + mt * 16 + ar;
        aoff[mt]  = (uint32_t)(row * 128);
        amask[mt] = (uint32_t)(row & 7);
    }
    #pragma unroll
    for (int p = 0; p < 4; p++) {          // each p covers n-tiles 2p, 2p+1
        const int row = wn * 64 + p * 16 + bn;
        boff[p]  = (uint32_t)(row * 128);
        bmask[p] = (uint32_t)(row & 7);
    }

    issue_slab(0, 0);
    issue_slab(1, 1);

    uint32_t afr[2][4][4];    // [buf][mt][frag]
    uint32_t bfr[2][8][2];    // [buf][nt][frag]

    // Load all 8 LDSM for k-step `ch` of slab at (abase, bbase) into buf.
    auto load_frags = [&](int buf, uint32_t abase, uint32_t bbase, int kk) {
        const uint32_t cha = (uint32_t)(kk * 2) + (uint32_t)ahalf;
        const uint32_t chb = (uint32_t)(kk * 2) + (uint32_t)bhalf;
        #pragma unroll
        for (int mt = 0; mt < 4; mt++)
            LDSM_X4(afr[buf][mt][0], afr[buf][mt][1], afr[buf][mt][2], afr[buf][mt][3],
                    abase + aoff[mt] + ((cha ^ amask[mt]) << 4));
        #pragma unroll
        for (int p = 0; p < 4; p++)
            LDSM_X4(bfr[buf][2*p][0], bfr[buf][2*p][1], bfr[buf][2*p+1][0], bfr[buf][2*p+1][1],
                    bbase + boff[p] + ((chb ^ bmask[p]) << 4));
    };

    #pragma unroll 1
    for (int s = 0; s < 4; s++) {
        if (s < 3) { CP_WAIT(1); } else { CP_WAIT(0); }
        __syncthreads();                  // slab s ready; buffer (s+2)%3 free
        if (s < 2) issue_slab(s + 2, (s + 2) % 3);

        const uint32_t abase = smem + (uint32_t)(s % 3) * BUF_BYTES;
        const uint32_t bbase = abase + SLAB_BYTES;

        load_frags(0, abase, bbase, 0);

        #pragma unroll
        for (int kk = 0; kk < 4; kk++) {
            const int cur = kk & 1;
            if (kk < 3) load_frags(cur ^ 1, abase, bbase, kk + 1);
            #pragma unroll
            for (int mt = 0; mt < 4; mt++)
                #pragma unroll
                for (int nt = 0; nt < 8; nt++)
                    MMA16816(acc[mt][nt][0], acc[mt][nt][1], acc[mt][nt][2], acc[mt][nt][3],
                             afr[cur][mt][0], afr[cur][mt][1], afr[cur][mt][2], afr[cur][mt][3],
                             bfr[cur][nt][0], bfr[cur][nt][1]);
        }
    }

    // ------------------- epilogue (fp16x2 exp2) -------------------
    __half2 rsum2[8];   // [mt*2+h] : lo+hi both belong to row
    __half2 csum2[8];   // [nt]     : lo -> col e0, hi -> col e1
    #pragma unroll
    for (int i = 0; i < 8; i++) rsum2[i] = __floats2half2_rn(0.0f, 0.0f);
    #pragma unroll
    for (int i = 0; i < 8; i++) csum2[i] = __floats2half2_rn(0.0f, 0.0f);

    const int q  = lane >> 2;
    const int e2 = (lane & 3) * 2;

    #pragma unroll
    for (int mt = 0; mt < 4; mt++) {
        #pragma unroll
        for (int nt = 0; nt < 8; nt++) {
            #pragma unroll
            for (int h = 0; h < 2; h++) {
                float v0 = acc[mt][nt][h * 2 + 0];
                float v1 = acc[mt][nt][h * 2 + 1];
                if (diag) {
                    const int rl = wm * 64 + mt * 16 + h * 8 + q;
                    const int c0 = wn * 64 + nt * 8 + e2;
                    if (rl == c0)     v0 = -100.0f;
                    if (rl == c0 + 1) v1 = -100.0f;
                }
                __half2 e = h2exp2(__floats2half2_rn(v0, v1));
                rsum2[mt * 2 + h] = __hadd2(rsum2[mt * 2 + h], e);
                csum2[nt]         = __hadd2(csum2[nt], e);
            }
        }
    }

    float rsum[8], csum[16];
    #pragma unroll
    for (int i = 0; i < 8; i++)
        rsum[i] = __low2float(rsum2[i]) + __high2float(rsum2[i]);
    #pragma unroll
    for (int nt = 0; nt < 8; nt++) {
        csum[nt * 2 + 0] = __low2float(csum2[nt]);
        csum[nt * 2 + 1] = __high2float(csum2[nt]);
    }

    #pragma unroll
    for (int i = 0; i < 8; i++) {
        rsum[i] += __shfl_xor_sync(0xffffffffu, rsum[i], 1);
        rsum[i] += __shfl_xor_sync(0xffffffffu, rsum[i], 2);
    }
    #pragma unroll
    for (int i = 0; i < 16; i++) {
        csum[i] += __shfl_xor_sync(0xffffffffu, csum[i], 4);
        csum[i] += __shfl_xor_sync(0xffffffffu, csum[i], 8);
        csum[i] += __shfl_xor_sync(0xffffffffu, csum[i], 16);
    }

    float* sred = reinterpret_cast<float*>(dyn_smem);            // [128][2]
    float* cred = sred + 128 * 2;                                // [128][2]
    __syncthreads();

    if ((lane & 3) == 0) {
        #pragma unroll
        for (int i = 0; i < 8; i++) {
            const int mt = i >> 1, h = i & 1;
            const int rl = wm * 64 + mt * 16 + h * 8 + q;
            sred[rl * 2 + wn] = rsum[i];
        }
    }
    if (!diag && (lane >> 2) == 0) {
        #pragma unroll
        for (int i = 0; i < 16; i++) {
            const int nt = i >> 1, e = i & 1;
            const int cl = wn * 64 + nt * 8 + (lane & 3) * 2 + e;
            cred[cl * 2 + wm] = csum[i];
        }
    }
    __syncthreads();

    // 128 threads: one row + one col each.
    {
        const float v = sred[tid * 2 + 0] + sred[tid * 2 + 1];
        atomicAdd(&g_rowsum[i0 + tid], v);
        if (!diag) {
            const float w2 = cred[tid * 2 + 0] + cred[tid * 2 + 1];
            atomicAdd(&g_rowsum[j0 + tid], w2);
        }
    }
}

// ---------------------------------------------------------------------------
// Kernel 3: final reduction. loss = mean(log(rowsum) - pos/T).
// ---------------------------------------------------------------------------
__global__ void k_loss(float* __restrict__ out) {
    const int i    = blockIdx.x * 256 + threadIdx.x;
    const int lane = threadIdx.x & 31;
    float val = logf(g_rowsum[i]) - g_pos[i & (BATCH - 1)] * INV_T;
    #pragma unroll
    for (int o = 16; o; o >>= 1) val += __shfl_xor_sync(0xffffffffu, val, o);
    if (lane == 0) atomicAdd(out, val * (1.0f / (float)NROWS));
}

// ---------------------------------------------------------------------------
extern "C" void kernel_launch(void* const* d_in, const int* in_sizes, int n_in,
                              void* d_out, int out_size) {
    const float* z = (const float*)d_in[0];
    float* out = (float*)d_out;

    cudaFuncSetAttribute(k_sim, cudaFuncAttributeMaxDynamicSharedMemorySize, DYN_SMEM);

    k_prep<<<BATCH / 8, 256>>>(z, out);
    k_sim<<<NTRI, 128, DYN_SMEM>>>();
    k_loss<<<NROWS / 256, 256>>>(out);
}